// round 6
// baseline (speedup 1.0000x reference)
#include <cuda_runtime.h>

#define NB 16
#define ND 64
#define NN 200
#define NT 48
#define NH 8

// intermediate h = x^T + LN(temporal_out):  (B,N,T,D)
__device__ float g_h[NB * NN * NT * ND];

// ---------------------------------------------------------------------------
// Kernel 1: per (b, n). conv1x3 q/k, linear v, 8-head attention over T=48
// (2 heads per sweep), W2 projection, LayerNorm + residual -> g_h.
// smem floats: xs[64][52]@0, wbuf@3328(6240), qs[64][52]@9568, ks[64][52]@12896,
//              vs[48][68]@16224, ss[2][48][52]@19488, aos[48][68]@24480
//              ys[48][65] overlays ss.   total 27744 floats = 110976 B
// ---------------------------------------------------------------------------
__global__ void __launch_bounds__(256, 2) temporal_kernel(
    const float* __restrict__ x,
    const float* __restrict__ Wq, const float* __restrict__ bq,
    const float* __restrict__ Wk, const float* __restrict__ bk,
    const float* __restrict__ W1, const float* __restrict__ b1,
    const float* __restrict__ W2, const float* __restrict__ b2,
    const float* __restrict__ g0, const float* __restrict__ beta0)
{
    extern __shared__ float sm[];
    float* xs   = sm;            // [64][52], col0/col49 zero pad
    float* wbuf = sm + 3328;     // 6240
    float* qs   = sm + 9568;     // [64][52]
    float* ks   = sm + 12896;    // [64][52]
    float* vs   = sm + 16224;    // [48][68]
    float* ss   = sm + 19488;    // [2][48][52]
    float* aos  = sm + 24480;    // [48][68]
    float* ys   = sm + 19488;    // [48][65] overlay on ss

    const int n   = blockIdx.x;
    const int b   = blockIdx.y;
    const int tid = threadIdx.x;
    const int d   = tid & 63;
    const int t0  = (tid >> 6) * 12;
    const int lane = tid & 31;
    const int warp = tid >> 5;

    // load x tile: x[b][e][n][t] -> xs[e][1+t]
    const float* xbase = x + ((long)(b * 64) * 200 + n) * 48;
    for (int i = tid; i < 64 * 48; i += 256) {
        int e = i / 48, t = i % 48;
        xs[e * 52 + 1 + t] = xbase[(long)e * 9600 + t];
    }
    if (tid < 128) {
        int e = tid & 63;
        xs[e * 52 + ((tid < 64) ? 0 : 49)] = 0.f;
    }

    // conv1x3 q/k as GEMM over (e,k); weights staged transposed in 16-e chunks
    float qa[12], ka[12];
    #pragma unroll
    for (int j = 0; j < 12; j++) { qa[j] = 0.f; ka[j] = 0.f; }

    for (int c = 0; c < 4; c++) {
        const int e0 = c * 16;
        __syncthreads();
        for (int i = tid; i < 64 * 48; i += 256) {
            int dd = i / 48, r = i % 48;
            wbuf[r * 65 + dd]        = Wq[dd * 192 + e0 * 3 + r];
            wbuf[3120 + r * 65 + dd] = Wk[dd * 192 + e0 * 3 + r];
        }
        __syncthreads();
        #pragma unroll
        for (int el = 0; el < 16; el++) {
            const float* xp = xs + (e0 + el) * 52 + t0;   // aligned
            float4 x0 = *(const float4*)(xp);
            float4 x1 = *(const float4*)(xp + 4);
            float4 x2 = *(const float4*)(xp + 8);
            float4 x3 = *(const float4*)(xp + 12);
            float xv[16] = {x0.x,x0.y,x0.z,x0.w, x1.x,x1.y,x1.z,x1.w,
                            x2.x,x2.y,x2.z,x2.w, x3.x,x3.y,x3.z,x3.w};
            float wq0 = wbuf[(el * 3 + 0) * 65 + d];
            float wq1 = wbuf[(el * 3 + 1) * 65 + d];
            float wq2 = wbuf[(el * 3 + 2) * 65 + d];
            float wk0 = wbuf[3120 + (el * 3 + 0) * 65 + d];
            float wk1 = wbuf[3120 + (el * 3 + 1) * 65 + d];
            float wk2 = wbuf[3120 + (el * 3 + 2) * 65 + d];
            #pragma unroll
            for (int j = 0; j < 12; j++) {
                qa[j] += wq0 * xv[j] + wq1 * xv[j + 1] + wq2 * xv[j + 2];
                ka[j] += wk0 * xv[j] + wk1 * xv[j + 1] + wk2 * xv[j + 2];
            }
        }
    }
    {
        float bqv = __ldg(bq + d), bkv = __ldg(bk + d);
        #pragma unroll
        for (int j = 0; j < 12; j++) {
            qs[d * 52 + t0 + j] = qa[j] + bqv;
            ks[d * 52 + t0 + j] = ka[j] + bkv;
        }
    }

    // v = x^T @ W1^T + b1
    __syncthreads();
    for (int i = tid; i < 4096; i += 256)
        wbuf[(i & 63) * 65 + (i >> 6)] = W1[i];   // wbuf[e*65+d] = W1[d][e]
    __syncthreads();
    {
        float va[12];
        float b1v = __ldg(b1 + d);
        #pragma unroll
        for (int j = 0; j < 12; j++) va[j] = b1v;
        for (int e = 0; e < 64; e++) {
            float w = wbuf[e * 65 + d];
            const float* xp = xs + e * 52 + t0;   // aligned; data at [1..12]
            float4 x0 = *(const float4*)(xp);
            float4 x1 = *(const float4*)(xp + 4);
            float4 x2 = *(const float4*)(xp + 8);
            float4 x3 = *(const float4*)(xp + 12);
            float xv[16] = {x0.x,x0.y,x0.z,x0.w, x1.x,x1.y,x1.z,x1.w,
                            x2.x,x2.y,x2.z,x2.w, x3.x,x3.y,x3.z,x3.w};
            #pragma unroll
            for (int j = 0; j < 12; j++) va[j] += w * xv[j + 1];
        }
        #pragma unroll
        for (int j = 0; j < 12; j++) vs[(t0 + j) * 68 + d] = va[j];
    }
    __syncthreads();

    // attention: 2 heads per sweep, 4 sweeps
    const float scale = 0.35355339059327373f; // 1/sqrt(8)
    for (int it = 0; it < 4; it++) {
        // scores: (hh, t, u0-8wide) = 2*48*6 = 576 items
        for (int w = tid; w < 576; w += 256) {
            int hh  = w / 288;
            int rem = w - hh * 288;
            int t   = rem / 6;
            int u0  = (rem - t * 6) * 8;
            int hd  = (it * 2 + hh) * 8;
            float4 a0 = make_float4(0.f,0.f,0.f,0.f);
            float4 a1 = make_float4(0.f,0.f,0.f,0.f);
            #pragma unroll
            for (int dk = 0; dk < 8; dk++) {
                int dd = hd + dk;
                float  qv = qs[dd * 52 + t];
                float4 k0 = *(const float4*)(ks + dd * 52 + u0);
                float4 k1 = *(const float4*)(ks + dd * 52 + u0 + 4);
                a0.x += qv * k0.x; a0.y += qv * k0.y; a0.z += qv * k0.z; a0.w += qv * k0.w;
                a1.x += qv * k1.x; a1.y += qv * k1.y; a1.z += qv * k1.z; a1.w += qv * k1.w;
            }
            a0.x *= scale; a0.y *= scale; a0.z *= scale; a0.w *= scale;
            a1.x *= scale; a1.y *= scale; a1.z *= scale; a1.w *= scale;
            float* srow = ss + (hh * 48 + t) * 52;
            *(float4*)(srow + u0)     = a0;
            *(float4*)(srow + u0 + 4) = a1;
        }
        __syncthreads();
        // softmax over 96 rows
        for (int rr = warp; rr < 96; rr += 8) {
            float* row = ss + rr * 52;
            float s1 = row[lane];
            float s2 = (lane < 16) ? row[lane + 32] : -1e30f;
            float mx = fmaxf(s1, s2);
            #pragma unroll
            for (int o = 16; o > 0; o >>= 1) mx = fmaxf(mx, __shfl_xor_sync(0xffffffffu, mx, o));
            float e1 = __expf(s1 - mx);
            float e2 = (lane < 16) ? __expf(s2 - mx) : 0.f;
            float sum = e1 + e2;
            #pragma unroll
            for (int o = 16; o > 0; o >>= 1) sum += __shfl_xor_sync(0xffffffffu, sum, o);
            float inv = 1.f / sum;
            row[lane] = e1 * inv;
            if (lane < 16) row[lane + 32] = e2 * inv;
        }
        __syncthreads();
        // PV: (t, dd4) = 48*4 items, 4 outputs each (float4)
        for (int w = tid; w < 192; w += 256) {
            int t  = w >> 2;
            int q4 = w & 3;
            int hh = q4 >> 1;
            int dd = (it * 2 + hh) * 8 + (q4 & 1) * 4;
            const float* prow = ss + (hh * 48 + t) * 52;
            float4 acc = make_float4(0.f,0.f,0.f,0.f);
            #pragma unroll
            for (int u0 = 0; u0 < 48; u0 += 4) {
                float4 p  = *(const float4*)(prow + u0);
                float4 v0 = *(const float4*)(vs + (u0 + 0) * 68 + dd);
                float4 v1 = *(const float4*)(vs + (u0 + 1) * 68 + dd);
                float4 v2 = *(const float4*)(vs + (u0 + 2) * 68 + dd);
                float4 v3 = *(const float4*)(vs + (u0 + 3) * 68 + dd);
                acc.x += p.x*v0.x + p.y*v1.x + p.z*v2.x + p.w*v3.x;
                acc.y += p.x*v0.y + p.y*v1.y + p.z*v2.y + p.w*v3.y;
                acc.z += p.x*v0.z + p.y*v1.z + p.z*v2.z + p.w*v3.z;
                acc.w += p.x*v0.w + p.y*v1.w + p.z*v2.w + p.w*v3.w;
            }
            *(float4*)(aos + t * 68 + dd) = acc;
        }
        __syncthreads();
    }

    // y = ao @ W2^T + b2
    for (int i = tid; i < 4096; i += 256)
        wbuf[(i & 63) * 65 + (i >> 6)] = W2[i];
    __syncthreads();
    {
        float ya[12];
        float b2v = __ldg(b2 + d);
        #pragma unroll
        for (int j = 0; j < 12; j++) ya[j] = b2v;
        for (int e = 0; e < 64; e++) {
            float w = wbuf[e * 65 + d];
            #pragma unroll
            for (int j = 0; j < 12; j++) ya[j] += w * aos[(t0 + j) * 68 + e];
        }
        #pragma unroll
        for (int j = 0; j < 12; j++) ys[(t0 + j) * 65 + d] = ya[j];
    }
    __syncthreads();

    // LayerNorm over d + residual x^T -> g_h
    float* hout = g_h + ((long)(b * 200 + n)) * 48 * 64;
    for (int t = warp; t < 48; t += 8) {
        float y1 = ys[t * 65 + lane];
        float y2 = ys[t * 65 + lane + 32];
        float s = y1 + y2;
        #pragma unroll
        for (int o = 16; o > 0; o >>= 1) s += __shfl_xor_sync(0xffffffffu, s, o);
        float mean = s * (1.f / 64.f);
        float d1 = y1 - mean, d2 = y2 - mean;
        float vv = d1 * d1 + d2 * d2;
        #pragma unroll
        for (int o = 16; o > 0; o >>= 1) vv += __shfl_xor_sync(0xffffffffu, vv, o);
        float rstd = rsqrtf(vv * (1.f / 64.f) + 1e-5f);
        float h1 = xs[lane * 52 + 1 + t]        + d1 * rstd * __ldg(g0 + lane)      + __ldg(beta0 + lane);
        float h2 = xs[(lane + 32) * 52 + 1 + t] + d2 * rstd * __ldg(g0 + lane + 32) + __ldg(beta0 + lane + 32);
        hout[t * 64 + lane]      = h1;
        hout[t * 64 + lane + 32] = h2;
    }
}

// ---------------------------------------------------------------------------
// Kernel 2: per (b, t, rowhalf). Flash-style spatial softmax-GCN; each block
// owns 100 output rows (all 200 keys/values), aggregate in registers (7x4),
// Theta GEMM + relu, LayerNorm + residual -> out.
// smem floats: hs[200][68]@0, S[100][68]@13600 (ThS[64][68] overlays),
//              rmax@20400, rsum@20500, fac@20600. total 20700 = 82800 B
// ---------------------------------------------------------------------------
__global__ void __launch_bounds__(256, 2) spatial_kernel(
    const float* __restrict__ adj, const float* __restrict__ Theta,
    const float* __restrict__ g1,  const float* __restrict__ beta1,
    float* __restrict__ out)
{
    extern __shared__ float sm[];
    float* hs   = sm;            // [200][68]
    float* S    = sm + 13600;    // [100][68]; later ThS [64][68]
    float* rmax = sm + 20400;    // 100
    float* rsum = sm + 20500;    // 100
    float* fac  = sm + 20600;    // 100

    const int t = blockIdx.x, b = blockIdx.y;
    const int r0 = blockIdx.z * 100;
    const int tid = threadIdx.x;
    const int tx = tid & 15, ty = tid >> 4;
    const int lane = tid & 31, warp = tid >> 5;

    const float* hbase = g_h + (long)b * 200 * 48 * 64 + (long)t * 64;
    for (int i = tid; i < 3200; i += 256) {
        int nn = i >> 4, d4 = (i & 15) * 4;
        *(float4*)(hs + nn * 68 + d4) = *(const float4*)(hbase + (long)nn * 3072 + d4);
    }
    if (tid < 100) { rmax[tid] = -1e30f; rsum[tid] = 0.f; }

    int  nl[7];
    bool rv[7];
    #pragma unroll
    for (int r = 0; r < 7; r++) {
        int v = ty + 16 * r;
        rv[r] = (v < 100);
        nl[r] = rv[r] ? v : 0;
    }

    float agg[7][4];
    #pragma unroll
    for (int r = 0; r < 7; r++)
        #pragma unroll
        for (int c = 0; c < 4; c++) agg[r][c] = 0.f;

    __syncthreads();

    for (int ci = 0; ci < 4; ci++) {
        const int m0 = ci * 64;
        const int MC = (ci == 3) ? 8 : 64;

        // scores for this block's rows vs columns m0..m0+MC
        {
            float sc[7][4];
            #pragma unroll
            for (int r = 0; r < 7; r++)
                #pragma unroll
                for (int c = 0; c < 4; c++) sc[r][c] = 0.f;
            int mc[4];
            #pragma unroll
            for (int c = 0; c < 4; c++) {
                int m = m0 + tx + 16 * c;
                mc[c] = (m < 200) ? m : 199;
            }
            for (int dd = 0; dd < 64; dd += 4) {
                float4 bb[4];
                #pragma unroll
                for (int c = 0; c < 4; c++)
                    bb[c] = *(const float4*)(hs + mc[c] * 68 + dd);
                #pragma unroll
                for (int r = 0; r < 7; r++) {
                    float4 av = *(const float4*)(hs + (r0 + nl[r]) * 68 + dd);
                    #pragma unroll
                    for (int c = 0; c < 4; c++)
                        sc[r][c] += av.x * bb[c].x + av.y * bb[c].y
                                  + av.z * bb[c].z + av.w * bb[c].w;
                }
            }
            #pragma unroll
            for (int r = 0; r < 7; r++) {
                if (!rv[r]) continue;
                #pragma unroll
                for (int c = 0; c < 4; c++) {
                    int m = m0 + tx + 16 * c;
                    if (m < 200) S[nl[r] * 68 + tx + 16 * c] = sc[r][c] * 0.125f;
                }
            }
        }
        __syncthreads();

        // online softmax + adjacency weighting (warp per row)
        for (int nn = warp; nn < 100; nn += 8) {
            float s1 = (lane < MC)      ? S[nn * 68 + lane]      : -1e30f;
            float s2 = (lane + 32 < MC) ? S[nn * 68 + lane + 32] : -1e30f;
            float mx = fmaxf(s1, s2);
            #pragma unroll
            for (int o = 16; o > 0; o >>= 1) mx = fmaxf(mx, __shfl_xor_sync(0xffffffffu, mx, o));
            float rm = rmax[nn];
            float nm = fmaxf(rm, mx);
            float f  = __expf(rm - nm);
            float e1 = (lane < MC)      ? __expf(s1 - nm) : 0.f;
            float e2 = (lane + 32 < MC) ? __expf(s2 - nm) : 0.f;
            float cs = e1 + e2;
            #pragma unroll
            for (int o = 16; o > 0; o >>= 1) cs += __shfl_xor_sync(0xffffffffu, cs, o);
            if (lane == 0) { rsum[nn] = rsum[nn] * f + cs; rmax[nn] = nm; fac[nn] = f; }
            const float* arow = adj + (long)(r0 + nn) * 200 + m0;
            if (lane < MC)      S[nn * 68 + lane]      = e1 * __ldg(arow + lane);
            if (lane + 32 < MC) S[nn * 68 + lane + 32] = e2 * __ldg(arow + lane + 32);
        }
        __syncthreads();

        // agg = agg*fac + P_chunk @ h_chunk
        {
            #pragma unroll
            for (int r = 0; r < 7; r++) {
                float f = fac[nl[r]];
                #pragma unroll
                for (int c = 0; c < 4; c++) agg[r][c] *= f;
            }
            for (int mb = 0; mb < MC; mb += 4) {
                float hb[4][4];
                #pragma unroll
                for (int j = 0; j < 4; j++)
                    #pragma unroll
                    for (int c = 0; c < 4; c++)
                        hb[j][c] = hs[(m0 + mb + j) * 68 + tx + 16 * c];
                #pragma unroll
                for (int r = 0; r < 7; r++) {
                    float4 pw = *(const float4*)(S + nl[r] * 68 + mb);
                    #pragma unroll
                    for (int c = 0; c < 4; c++)
                        agg[r][c] += pw.x * hb[0][c] + pw.y * hb[1][c]
                                   + pw.z * hb[2][c] + pw.w * hb[3][c];
                }
            }
        }
        __syncthreads();
    }

    // finalize agg /= (rsum * sqrt(D)); park in hs rows 0..99 (local scratch)
    #pragma unroll
    for (int r = 0; r < 7; r++) {
        float inv = 1.f / (rsum[nl[r]] * 8.f);
        #pragma unroll
        for (int c = 0; c < 4; c++) agg[r][c] *= inv;
    }
    #pragma unroll
    for (int r = 0; r < 7; r++) {
        if (!rv[r]) continue;
        #pragma unroll
        for (int c = 0; c < 4; c++) hs[nl[r] * 68 + tx + 16 * c] = agg[r][c];
    }
    // stage Theta rows: ThS[j*68 + dd] = Theta[j][dd]
    for (int i = tid; i < 4096; i += 256)
        S[(i >> 6) * 68 + (i & 63)] = Theta[i];
    __syncthreads();

    // G = relu(agg @ Theta^T)
    float g[7][4];
    #pragma unroll
    for (int r = 0; r < 7; r++)
        #pragma unroll
        for (int c = 0; c < 4; c++) g[r][c] = 0.f;
    for (int dd = 0; dd < 64; dd += 4) {
        float4 tb[4];
        #pragma unroll
        for (int c = 0; c < 4; c++)
            tb[c] = *(const float4*)(S + (tx + 16 * c) * 68 + dd);
        #pragma unroll
        for (int r = 0; r < 7; r++) {
            float4 av = *(const float4*)(hs + nl[r] * 68 + dd);
            #pragma unroll
            for (int c = 0; c < 4; c++)
                g[r][c] += av.x * tb[c].x + av.y * tb[c].y
                         + av.z * tb[c].z + av.w * tb[c].w;
        }
    }
    #pragma unroll
    for (int r = 0; r < 7; r++)
        #pragma unroll
        for (int c = 0; c < 4; c++) g[r][c] = fmaxf(g[r][c], 0.f);

    // LayerNorm over j (width-16 shuffles) + residual (h from gmem) + store
    float* obase = out + (long)b * 200 * 3072 + (long)t * 64;
    #pragma unroll
    for (int r = 0; r < 7; r++) {
        if (!rv[r]) continue;
        int ng = r0 + nl[r];
        float s = g[r][0] + g[r][1] + g[r][2] + g[r][3];
        #pragma unroll
        for (int o = 8; o > 0; o >>= 1) s += __shfl_xor_sync(0xffffffffu, s, o, 16);
        float mean = s * (1.f / 64.f);
        float vv = 0.f;
        #pragma unroll
        for (int c = 0; c < 4; c++) { float dg = g[r][c] - mean; vv += dg * dg; }
        #pragma unroll
        for (int o = 8; o > 0; o >>= 1) vv += __shfl_xor_sync(0xffffffffu, vv, o, 16);
        float rstd = rsqrtf(vv * (1.f / 64.f) + 1e-5f);
        #pragma unroll
        for (int c = 0; c < 4; c++) {
            int j = tx + 16 * c;
            float hv = hbase[(long)ng * 3072 + j];
            obase[(long)ng * 3072 + j] =
                hv + (g[r][c] - mean) * rstd * __ldg(g1 + j) + __ldg(beta1 + j);
        }
    }
}

// ---------------------------------------------------------------------------
extern "C" void kernel_launch(void* const* d_in, const int* in_sizes, int n_in,
                              void* d_out, int out_size)
{
    const float* x     = (const float*)d_in[0];
    const float* adj   = (const float*)d_in[1];
    const float* Wq    = (const float*)d_in[2];
    const float* bq    = (const float*)d_in[3];
    const float* Wk    = (const float*)d_in[4];
    const float* bk    = (const float*)d_in[5];
    const float* W1    = (const float*)d_in[6];
    const float* b1    = (const float*)d_in[7];
    const float* W2    = (const float*)d_in[8];
    const float* b2    = (const float*)d_in[9];
    const float* Theta = (const float*)d_in[10];
    const float* g0    = (const float*)d_in[11];
    const float* beta0 = (const float*)d_in[12];
    const float* g1    = (const float*)d_in[13];
    const float* beta1 = (const float*)d_in[14];
    float* out = (float*)d_out;

    const int SMEM_T = 27744 * 4;   // 110976 B
    const int SMEM_S = 20700 * 4;   //  82800 B
    cudaFuncSetAttribute(temporal_kernel,
                         cudaFuncAttributeMaxDynamicSharedMemorySize, SMEM_T);
    cudaFuncSetAttribute(spatial_kernel,
                         cudaFuncAttributeMaxDynamicSharedMemorySize, SMEM_S);

    temporal_kernel<<<dim3(NN, NB), 256, SMEM_T>>>(
        x, Wq, bq, Wk, bk, W1, b1, W2, b2, g0, beta0);
    spatial_kernel<<<dim3(NT, NB, 2), 256, SMEM_S>>>(
        adj, Theta, g1, beta1, out);
}

// round 10
// speedup vs baseline: 1.5261x; 1.5261x over previous
#include <cuda_runtime.h>

#define NB 16
#define ND 64
#define NN 200
#define NT 48
#define NH 8

// intermediate h = x^T + LN(temporal_out):  (B,N,T,D)
__device__ float g_h[NB * NN * NT * ND];

// ---------------------------------------------------------------------------
// Kernel 1: per (b, n). conv1x3 q/k, linear v, 8-head attention over T=48
// (thread-per-(head,t) row: scores+softmax+PV all in registers, no barriers),
// W2 projection, LayerNorm + residual -> g_h.
// smem floats: xs[64][52]@0, qs[64][52]@3328, ks[64][52]@6656, vs[48][68]@9984,
//              aos[48][68]@13248, wbuf[6240]@16512, ys[48][65]@22752
//              total 25872 floats = 103488 B  (2 blocks/SM)
// ---------------------------------------------------------------------------
__global__ void __launch_bounds__(256, 2) temporal_kernel(
    const float* __restrict__ x,
    const float* __restrict__ Wq, const float* __restrict__ bq,
    const float* __restrict__ Wk, const float* __restrict__ bk,
    const float* __restrict__ W1, const float* __restrict__ b1,
    const float* __restrict__ W2, const float* __restrict__ b2,
    const float* __restrict__ g0, const float* __restrict__ beta0)
{
    extern __shared__ float sm[];
    float* xs   = sm;            // [64][52], col0/col49 zero pad
    float* qs   = sm + 3328;     // [64][52]
    float* ks   = sm + 6656;     // [64][52]
    float* vs   = sm + 9984;     // [48][68]
    float* aos  = sm + 13248;    // [48][68]
    float* wbuf = sm + 16512;    // 6240
    float* ys   = sm + 22752;    // [48][65]

    const int n   = blockIdx.x;
    const int b   = blockIdx.y;
    const int tid = threadIdx.x;
    const int d   = tid & 63;
    const int t0  = (tid >> 6) * 12;
    const int lane = tid & 31;
    const int warp = tid >> 5;

    // load x tile: x[b][e][n][t] -> xs[e][1+t]
    const float* xbase = x + ((long)(b * 64) * 200 + n) * 48;
    for (int i = tid; i < 64 * 48; i += 256) {
        int e = i / 48, t = i % 48;
        xs[e * 52 + 1 + t] = xbase[(long)e * 9600 + t];
    }
    if (tid < 128) {
        int e = tid & 63;
        xs[e * 52 + ((tid < 64) ? 0 : 49)] = 0.f;
    }

    // conv1x3 q/k as GEMM over (e,k); weights staged transposed in 16-e chunks
    float qa[12], ka[12];
    #pragma unroll
    for (int j = 0; j < 12; j++) { qa[j] = 0.f; ka[j] = 0.f; }

    for (int c = 0; c < 4; c++) {
        const int e0 = c * 16;
        __syncthreads();
        for (int i = tid; i < 64 * 48; i += 256) {
            int dd = i / 48, r = i % 48;
            wbuf[r * 65 + dd]        = Wq[dd * 192 + e0 * 3 + r];
            wbuf[3120 + r * 65 + dd] = Wk[dd * 192 + e0 * 3 + r];
        }
        __syncthreads();
        #pragma unroll
        for (int el = 0; el < 16; el++) {
            const float* xp = xs + (e0 + el) * 52 + t0;   // aligned
            float4 x0 = *(const float4*)(xp);
            float4 x1 = *(const float4*)(xp + 4);
            float4 x2 = *(const float4*)(xp + 8);
            float4 x3 = *(const float4*)(xp + 12);
            float xv[16] = {x0.x,x0.y,x0.z,x0.w, x1.x,x1.y,x1.z,x1.w,
                            x2.x,x2.y,x2.z,x2.w, x3.x,x3.y,x3.z,x3.w};
            float wq0 = wbuf[(el * 3 + 0) * 65 + d];
            float wq1 = wbuf[(el * 3 + 1) * 65 + d];
            float wq2 = wbuf[(el * 3 + 2) * 65 + d];
            float wk0 = wbuf[3120 + (el * 3 + 0) * 65 + d];
            float wk1 = wbuf[3120 + (el * 3 + 1) * 65 + d];
            float wk2 = wbuf[3120 + (el * 3 + 2) * 65 + d];
            #pragma unroll
            for (int j = 0; j < 12; j++) {
                qa[j] += wq0 * xv[j] + wq1 * xv[j + 1] + wq2 * xv[j + 2];
                ka[j] += wk0 * xv[j] + wk1 * xv[j + 1] + wk2 * xv[j + 2];
            }
        }
    }
    {
        float bqv = __ldg(bq + d), bkv = __ldg(bk + d);
        #pragma unroll
        for (int j = 0; j < 12; j++) {
            qs[d * 52 + t0 + j] = qa[j] + bqv;
            ks[d * 52 + t0 + j] = ka[j] + bkv;
        }
    }

    // v = x^T @ W1^T + b1
    __syncthreads();
    for (int i = tid; i < 4096; i += 256)
        wbuf[(i & 63) * 65 + (i >> 6)] = W1[i];   // wbuf[e*65+d] = W1[d][e]
    __syncthreads();
    {
        float va[12];
        float b1v = __ldg(b1 + d);
        #pragma unroll
        for (int j = 0; j < 12; j++) va[j] = b1v;
        for (int e = 0; e < 64; e++) {
            float w = wbuf[e * 65 + d];
            const float* xp = xs + e * 52 + t0;   // data at [1..12]
            float4 x0 = *(const float4*)(xp);
            float4 x1 = *(const float4*)(xp + 4);
            float4 x2 = *(const float4*)(xp + 8);
            float4 x3 = *(const float4*)(xp + 12);
            float xv[16] = {x0.x,x0.y,x0.z,x0.w, x1.x,x1.y,x1.z,x1.w,
                            x2.x,x2.y,x2.z,x2.w, x3.x,x3.y,x3.z,x3.w};
            #pragma unroll
            for (int j = 0; j < 12; j++) va[j] += w * xv[j + 1];
        }
        #pragma unroll
        for (int j = 0; j < 12; j++) vs[(t0 + j) * 68 + d] = va[j];
    }
    __syncthreads();   // qs, ks, vs ready

    // --- attention: thread = (head-half, t); two sweeps of 4 heads.
    //     threads 192..255 prefetch W2 into wbuf meanwhile.
    const float scale = 0.35355339059327373f; // 1/sqrt(8)
    if (tid < 192) {
        const int t  = tid % 48;
        const int hh = tid / 48;       // 0..3
        #pragma unroll
        for (int sw = 0; sw < 2; sw++) {
            const int hd = (sw * 4 + hh) * 8;
            // q column for this t
            float q[8];
            #pragma unroll
            for (int dk = 0; dk < 8; dk++) q[dk] = qs[(hd + dk) * 52 + t];
            // scores (registers)
            float s[48];
            #pragma unroll
            for (int u4 = 0; u4 < 12; u4++) {
                float4 a = make_float4(0.f, 0.f, 0.f, 0.f);
                #pragma unroll
                for (int dk = 0; dk < 8; dk++) {
                    float4 kv = *(const float4*)(ks + (hd + dk) * 52 + u4 * 4);
                    a.x += q[dk] * kv.x; a.y += q[dk] * kv.y;
                    a.z += q[dk] * kv.z; a.w += q[dk] * kv.w;
                }
                s[u4 * 4 + 0] = a.x * scale; s[u4 * 4 + 1] = a.y * scale;
                s[u4 * 4 + 2] = a.z * scale; s[u4 * 4 + 3] = a.w * scale;
            }
            // serial softmax in registers (unnormalized; fold 1/sum into PV)
            float mx = s[0];
            #pragma unroll
            for (int u = 1; u < 48; u++) mx = fmaxf(mx, s[u]);
            float sum = 0.f;
            #pragma unroll
            for (int u = 0; u < 48; u++) { s[u] = __expf(s[u] - mx); sum += s[u]; }
            float inv = 1.f / sum;
            // PV
            float4 a0 = make_float4(0.f, 0.f, 0.f, 0.f);
            float4 a1 = make_float4(0.f, 0.f, 0.f, 0.f);
            #pragma unroll
            for (int u = 0; u < 48; u++) {
                float p  = s[u];
                float4 v0 = *(const float4*)(vs + u * 68 + hd);
                float4 v1 = *(const float4*)(vs + u * 68 + hd + 4);
                a0.x += p * v0.x; a0.y += p * v0.y; a0.z += p * v0.z; a0.w += p * v0.w;
                a1.x += p * v1.x; a1.y += p * v1.y; a1.z += p * v1.z; a1.w += p * v1.w;
            }
            a0.x *= inv; a0.y *= inv; a0.z *= inv; a0.w *= inv;
            a1.x *= inv; a1.y *= inv; a1.z *= inv; a1.w *= inv;
            *(float4*)(aos + t * 68 + hd)     = a0;
            *(float4*)(aos + t * 68 + hd + 4) = a1;
        }
    } else {
        // prefetch W2 transposed into wbuf: wbuf[e*65+d] = W2[d][e]
        for (int i = tid - 192; i < 4096; i += 64)
            wbuf[(i & 63) * 65 + (i >> 6)] = W2[i];
    }
    __syncthreads();

    // y = ao @ W2^T + b2
    {
        float ya[12];
        float b2v = __ldg(b2 + d);
        #pragma unroll
        for (int j = 0; j < 12; j++) ya[j] = b2v;
        for (int e = 0; e < 64; e++) {
            float w = wbuf[e * 65 + d];
            #pragma unroll
            for (int j = 0; j < 12; j++) ya[j] += w * aos[(t0 + j) * 68 + e];
        }
        #pragma unroll
        for (int j = 0; j < 12; j++) ys[(t0 + j) * 65 + d] = ya[j];
    }
    __syncthreads();

    // LayerNorm over d + residual x^T -> g_h
    float* hout = g_h + ((long)(b * 200 + n)) * 48 * 64;
    for (int t = warp; t < 48; t += 8) {
        float y1 = ys[t * 65 + lane];
        float y2 = ys[t * 65 + lane + 32];
        float s = y1 + y2;
        #pragma unroll
        for (int o = 16; o > 0; o >>= 1) s += __shfl_xor_sync(0xffffffffu, s, o);
        float mean = s * (1.f / 64.f);
        float d1 = y1 - mean, d2 = y2 - mean;
        float vv = d1 * d1 + d2 * d2;
        #pragma unroll
        for (int o = 16; o > 0; o >>= 1) vv += __shfl_xor_sync(0xffffffffu, vv, o);
        float rstd = rsqrtf(vv * (1.f / 64.f) + 1e-5f);
        float h1 = xs[lane * 52 + 1 + t]        + d1 * rstd * __ldg(g0 + lane)      + __ldg(beta0 + lane);
        float h2 = xs[(lane + 32) * 52 + 1 + t] + d2 * rstd * __ldg(g0 + lane + 32) + __ldg(beta0 + lane + 32);
        hout[t * 64 + lane]      = h1;
        hout[t * 64 + lane + 32] = h2;
    }
}

// ---------------------------------------------------------------------------
// Kernel 2: per (b, t, rowhalf). Spatial softmax-GCN, 100 rows/block.
// Online softmax state (rmax/rsum/factor) lives in REGISTERS (each score row
// is owned by one 16-lane half-warp; reductions = width-16 shuffles), so the
// flash loop needs no __syncthreads at all — only __syncwarp.
// smem floats: hs[200][68]@0 (13600), S[100][68]@13600 (6800; ThS[64][68]
// overlays) => 20400 floats = 81600 B  (2 blocks/SM)
// ---------------------------------------------------------------------------
__global__ void __launch_bounds__(256, 2) spatial_kernel(
    const float* __restrict__ adj, const float* __restrict__ Theta,
    const float* __restrict__ g1,  const float* __restrict__ beta1,
    float* __restrict__ out)
{
    extern __shared__ float sm[];
    float* hs = sm;            // [200][68]
    float* S  = sm + 13600;    // [100][68] P buffer; later ThS[64][68] dd-major

    const int t = blockIdx.x, b = blockIdx.y;
    const int r0 = blockIdx.z * 100;
    const int tid = threadIdx.x;
    const int tx = tid & 15, ty = tid >> 4;

    const float* hbase = g_h + (long)b * 200 * 48 * 64 + (long)t * 64;
    for (int i = tid; i < 3200; i += 256) {
        int nn = i >> 4, d4 = (i & 15) * 4;
        *(float4*)(hs + nn * 68 + d4) = *(const float4*)(hbase + (long)nn * 3072 + d4);
    }

    int  nl[7], slc[7];
    bool rv[7];
    #pragma unroll
    for (int r = 0; r < 7; r++) {
        int v = ty + 16 * r;
        rv[r]  = (v < 100);
        slc[r] = rv[r] ? v : 99;
        nl[r]  = slc[r];
    }

    float agg[7][4], rm[7], rs[7];
    #pragma unroll
    for (int r = 0; r < 7; r++) {
        rm[r] = -1e30f; rs[r] = 0.f;
        #pragma unroll
        for (int c = 0; c < 4; c++) agg[r][c] = 0.f;
    }

    __syncthreads();   // hs ready

    for (int ci = 0; ci < 4; ci++) {
        const int m0 = ci * 64;
        const int MC = (ci == 3) ? 8 : 64;
        __syncwarp();  // P rows from previous chunk fully consumed

        // ---- scores: rows r0+nl[r], cols m = m0+tx+16c ----
        float sc[7][4];
        #pragma unroll
        for (int r = 0; r < 7; r++)
            #pragma unroll
            for (int c = 0; c < 4; c++) sc[r][c] = 0.f;
        int  mc[4]; bool mv[4];
        #pragma unroll
        for (int c = 0; c < 4; c++) {
            int m = m0 + tx + 16 * c;
            mv[c] = (m < 200);
            mc[c] = mv[c] ? m : 199;
        }
        for (int dd = 0; dd < 64; dd += 4) {
            float4 bb[4];
            #pragma unroll
            for (int c = 0; c < 4; c++)
                bb[c] = *(const float4*)(hs + mc[c] * 68 + dd);
            #pragma unroll
            for (int r = 0; r < 7; r++) {
                float4 av = *(const float4*)(hs + (r0 + slc[r]) * 68 + dd);
                #pragma unroll
                for (int c = 0; c < 4; c++)
                    sc[r][c] += av.x * bb[c].x + av.y * bb[c].y
                              + av.z * bb[c].z + av.w * bb[c].w;
            }
        }

        // ---- register online softmax per row (width-16 shuffles) + P store
        #pragma unroll
        for (int r = 0; r < 7; r++) {
            float e[4];
            float mx = -1e30f;
            #pragma unroll
            for (int c = 0; c < 4; c++) {
                sc[r][c] = mv[c] ? sc[r][c] * 0.125f : -1e30f;
                mx = fmaxf(mx, sc[r][c]);
            }
            #pragma unroll
            for (int o = 8; o > 0; o >>= 1)
                mx = fmaxf(mx, __shfl_xor_sync(0xffffffffu, mx, o, 16));
            float nm = fmaxf(rm[r], mx);
            float f  = __expf(rm[r] - nm);
            rm[r] = nm;
            float cs = 0.f;
            #pragma unroll
            for (int c = 0; c < 4; c++) { e[c] = __expf(sc[r][c] - nm); cs += e[c]; }
            #pragma unroll
            for (int o = 8; o > 0; o >>= 1)
                cs += __shfl_xor_sync(0xffffffffu, cs, o, 16);
            rs[r] = rs[r] * f + cs;
            #pragma unroll
            for (int c = 0; c < 4; c++) agg[r][c] *= f;
            if (rv[r]) {
                const float* arow = adj + (long)(r0 + nl[r]) * 200 + m0;
                #pragma unroll
                for (int c = 0; c < 4; c++)
                    if (mv[c])
                        S[nl[r] * 68 + tx + 16 * c] = e[c] * __ldg(arow + tx + 16 * c);
            }
        }
        __syncwarp();   // P rows visible within owning half-warp

        // ---- agg += P_chunk @ h_chunk  (output cols dd = 4tx+c) ----
        for (int mb = 0; mb < MC; mb += 4) {
            float4 hb[4];
            #pragma unroll
            for (int j = 0; j < 4; j++)
                hb[j] = *(const float4*)(hs + (m0 + mb + j) * 68 + 4 * tx);
            #pragma unroll
            for (int r = 0; r < 7; r++) {
                float4 pw = *(const float4*)(S + slc[r] * 68 + mb);
                agg[r][0] += pw.x * hb[0].x + pw.y * hb[1].x + pw.z * hb[2].x + pw.w * hb[3].x;
                agg[r][1] += pw.x * hb[0].y + pw.y * hb[1].y + pw.z * hb[2].y + pw.w * hb[3].y;
                agg[r][2] += pw.x * hb[0].z + pw.y * hb[1].z + pw.z * hb[2].z + pw.w * hb[3].z;
                agg[r][3] += pw.x * hb[0].w + pw.y * hb[1].w + pw.z * hb[2].w + pw.w * hb[3].w;
            }
        }
    }

    __syncthreads();   // done reading hs / S everywhere

    // finalize agg /= (rsum * sqrt(D)); park rows into hs[0..99]
    #pragma unroll
    for (int r = 0; r < 7; r++) {
        float inv = 1.f / (rs[r] * 8.f);
        if (rv[r]) {
            float4 v = make_float4(agg[r][0] * inv, agg[r][1] * inv,
                                   agg[r][2] * inv, agg[r][3] * inv);
            *(float4*)(hs + nl[r] * 68 + 4 * tx) = v;
        }
    }
    // stage Theta dd-major: ThS[dd*68 + j] = Theta[j][dd]
    for (int i = tid; i < 4096; i += 256)
        S[(i & 63) * 68 + (i >> 6)] = Theta[i];
    __syncthreads();

    // G = relu(agg @ Theta^T), thread cols j = 4tx+c
    float g[7][4];
    #pragma unroll
    for (int r = 0; r < 7; r++)
        #pragma unroll
        for (int c = 0; c < 4; c++) g[r][c] = 0.f;
    for (int dd = 0; dd < 64; dd += 4) {
        float4 tb[4];
        #pragma unroll
        for (int i = 0; i < 4; i++)
            tb[i] = *(const float4*)(S + (dd + i) * 68 + 4 * tx);
        #pragma unroll
        for (int r = 0; r < 7; r++) {
            float4 av = *(const float4*)(hs + slc[r] * 68 + dd);
            g[r][0] += av.x * tb[0].x + av.y * tb[1].x + av.z * tb[2].x + av.w * tb[3].x;
            g[r][1] += av.x * tb[0].y + av.y * tb[1].y + av.z * tb[2].y + av.w * tb[3].y;
            g[r][2] += av.x * tb[0].z + av.y * tb[1].z + av.z * tb[2].z + av.w * tb[3].z;
            g[r][3] += av.x * tb[0].w + av.y * tb[1].w + av.z * tb[2].w + av.w * tb[3].w;
        }
    }
    #pragma unroll
    for (int r = 0; r < 7; r++)
        #pragma unroll
        for (int c = 0; c < 4; c++) g[r][c] = fmaxf(g[r][c], 0.f);

    // LayerNorm over j + residual (float4 gmem) + store
    float* obase = out + (long)b * 200 * 3072 + (long)t * 64;
    float4 g1v = *(const float4*)(g1 + 4 * tx);
    float4 b1v = *(const float4*)(beta1 + 4 * tx);
    #pragma unroll
    for (int r = 0; r < 7; r++) {
        if (!rv[r]) continue;
        int ng = r0 + nl[r];
        float s = g[r][0] + g[r][1] + g[r][2] + g[r][3];
        #pragma unroll
        for (int o = 8; o > 0; o >>= 1) s += __shfl_xor_sync(0xffffffffu, s, o, 16);
        float mean = s * (1.f / 64.f);
        float vv = 0.f;
        #pragma unroll
        for (int c = 0; c < 4; c++) { float dg = g[r][c] - mean; vv += dg * dg; }
        #pragma unroll
        for (int o = 8; o > 0; o >>= 1) vv += __shfl_xor_sync(0xffffffffu, vv, o, 16);
        float rstd = rsqrtf(vv * (1.f / 64.f) + 1e-5f);
        float4 hv = *(const float4*)(hbase + (long)ng * 3072 + 4 * tx);
        float4 ov;
        ov.x = hv.x + (g[r][0] - mean) * rstd * g1v.x + b1v.x;
        ov.y = hv.y + (g[r][1] - mean) * rstd * g1v.y + b1v.y;
        ov.z = hv.z + (g[r][2] - mean) * rstd * g1v.z + b1v.z;
        ov.w = hv.w + (g[r][3] - mean) * rstd * g1v.w + b1v.w;
        *(float4*)(obase + (long)ng * 3072 + 4 * tx) = ov;
    }
}

// ---------------------------------------------------------------------------
extern "C" void kernel_launch(void* const* d_in, const int* in_sizes, int n_in,
                              void* d_out, int out_size)
{
    const float* x     = (const float*)d_in[0];
    const float* adj   = (const float*)d_in[1];
    const float* Wq    = (const float*)d_in[2];
    const float* bq    = (const float*)d_in[3];
    const float* Wk    = (const float*)d_in[4];
    const float* bk    = (const float*)d_in[5];
    const float* W1    = (const float*)d_in[6];
    const float* b1    = (const float*)d_in[7];
    const float* W2    = (const float*)d_in[8];
    const float* b2    = (const float*)d_in[9];
    const float* Theta = (const float*)d_in[10];
    const float* g0    = (const float*)d_in[11];
    const float* beta0 = (const float*)d_in[12];
    const float* g1    = (const float*)d_in[13];
    const float* beta1 = (const float*)d_in[14];
    float* out = (float*)d_out;

    const int SMEM_T = 25872 * 4;   // 103488 B
    const int SMEM_S = 20400 * 4;   //  81600 B
    cudaFuncSetAttribute(temporal_kernel,
                         cudaFuncAttributeMaxDynamicSharedMemorySize, SMEM_T);
    cudaFuncSetAttribute(spatial_kernel,
                         cudaFuncAttributeMaxDynamicSharedMemorySize, SMEM_S);

    temporal_kernel<<<dim3(NN, NB), 256, SMEM_T>>>(
        x, Wq, bq, Wk, bk, W1, b1, W2, b2, g0, beta0);
    spatial_kernel<<<dim3(NT, NB, 2), 256, SMEM_S>>>(
        adj, Theta, g1, beta1, out);
}

// round 12
// speedup vs baseline: 1.5474x; 1.0139x over previous
#include <cuda_runtime.h>

#define NB 16
#define ND 64
#define NN 200
#define NT 48
#define NH 8

// intermediate h = x^T + LN(temporal_out):  (B,N,T,D)
__device__ float g_h[NB * NN * NT * ND];

// pre-transposed weights (written by prep_weights each launch)
__device__ float2 g_wqkT[192 * 64];   // [(e*3+k)][d] -> (Wq, Wk)
__device__ float  g_w1T[64 * 64];     // [e][d] = W1[d][e]
__device__ float  g_w2T[64 * 64];     // [e][d] = W2[d][e]

__global__ void prep_weights(const float* __restrict__ Wq,
                             const float* __restrict__ Wk,
                             const float* __restrict__ W1,
                             const float* __restrict__ W2)
{
    int i = blockIdx.x * 256 + threadIdx.x;
    if (i < 12288) {
        int r = i >> 6, d = i & 63;          // r = e*3+k
        float2 v;
        v.x = Wq[d * 192 + r];
        v.y = Wk[d * 192 + r];
        g_wqkT[i] = v;
    }
    if (i < 4096) {
        int e = i >> 6, d = i & 63;
        g_w1T[i] = W1[d * 64 + e];
        g_w2T[i] = W2[d * 64 + e];
    }
}

// ---------------------------------------------------------------------------
// Kernel 1: per (b, n). conv1x3 q/k (single pass, weights via LDG), linear v,
// 8-head attention over T=48 (rows in registers, no barriers), W2 projection
// (float4 over e), LayerNorm + residual -> g_h.
// smem floats: xs[64][52]@0, qs[64][52]@3328, ks[64][52]@6656, vs[48][68]@9984,
//              aos[48][68]@13248, ys[48][68]@16512  => 19776 floats = 79104 B
// ---------------------------------------------------------------------------
__global__ void __launch_bounds__(256, 2) temporal_kernel(
    const float* __restrict__ x,
    const float* __restrict__ bq, const float* __restrict__ bk,
    const float* __restrict__ b1, const float* __restrict__ b2,
    const float* __restrict__ g0, const float* __restrict__ beta0)
{
    extern __shared__ float sm[];
    float* xs   = sm;            // [64][52], col0/col49 zero pad
    float* qs   = sm + 3328;     // [64][52]
    float* ks   = sm + 6656;     // [64][52]
    float* vs   = sm + 9984;     // [48][68]
    float* aos  = sm + 13248;    // [48][68]
    float* ys   = sm + 16512;    // [48][68]

    const int n   = blockIdx.x;
    const int b   = blockIdx.y;
    const int tid = threadIdx.x;
    const int d   = tid & 63;
    const int t0  = (tid >> 6) * 12;
    const int lane = tid & 31;
    const int warp = tid >> 5;

    // load x tile: x[b][e][n][t] -> xs[e][1+t]
    const float* xbase = x + ((long)(b * 64) * 200 + n) * 48;
    for (int i = tid; i < 64 * 48; i += 256) {
        int e = i / 48, t = i % 48;
        xs[e * 52 + 1 + t] = xbase[(long)e * 9600 + t];
    }
    if (tid < 128) {
        int e = tid & 63;
        xs[e * 52 + ((tid < 64) ? 0 : 49)] = 0.f;
    }
    __syncthreads();   // xs ready

    // ---- conv1x3 q/k: single pass over e, weights via LDG (pre-transposed)
    float qa[12], ka[12];
    #pragma unroll
    for (int j = 0; j < 12; j++) { qa[j] = 0.f; ka[j] = 0.f; }

    #pragma unroll 2
    for (int el = 0; el < 64; el++) {
        const float2* wr = g_wqkT + el * 3 * 64 + d;
        float2 w0 = __ldg(wr);
        float2 w1 = __ldg(wr + 64);
        float2 w2 = __ldg(wr + 128);
        const float* xp = xs + el * 52 + t0;   // aligned; padded cols t0..t0+15
        float4 x0 = *(const float4*)(xp);
        float4 x1 = *(const float4*)(xp + 4);
        float4 x2 = *(const float4*)(xp + 8);
        float4 x3 = *(const float4*)(xp + 12);
        float xv[16] = {x0.x,x0.y,x0.z,x0.w, x1.x,x1.y,x1.z,x1.w,
                        x2.x,x2.y,x2.z,x2.w, x3.x,x3.y,x3.z,x3.w};
        #pragma unroll
        for (int j = 0; j < 12; j++) {
            qa[j] += w0.x * xv[j] + w1.x * xv[j + 1] + w2.x * xv[j + 2];
            ka[j] += w0.y * xv[j] + w1.y * xv[j + 1] + w2.y * xv[j + 2];
        }
    }
    {
        float bqv = __ldg(bq + d), bkv = __ldg(bk + d);
        float4* qrow = (float4*)(qs + d * 52 + t0);
        float4* krow = (float4*)(ks + d * 52 + t0);
        qrow[0] = make_float4(qa[0]+bqv, qa[1]+bqv, qa[2]+bqv,  qa[3]+bqv);
        qrow[1] = make_float4(qa[4]+bqv, qa[5]+bqv, qa[6]+bqv,  qa[7]+bqv);
        qrow[2] = make_float4(qa[8]+bqv, qa[9]+bqv, qa[10]+bqv, qa[11]+bqv);
        krow[0] = make_float4(ka[0]+bkv, ka[1]+bkv, ka[2]+bkv,  ka[3]+bkv);
        krow[1] = make_float4(ka[4]+bkv, ka[5]+bkv, ka[6]+bkv,  ka[7]+bkv);
        krow[2] = make_float4(ka[8]+bkv, ka[9]+bkv, ka[10]+bkv, ka[11]+bkv);
    }

    // ---- v = x^T @ W1^T + b1 (weights via LDG)
    {
        float va[12];
        float b1v = __ldg(b1 + d);
        #pragma unroll
        for (int j = 0; j < 12; j++) va[j] = b1v;
        #pragma unroll 2
        for (int e = 0; e < 64; e++) {
            float w = __ldg(g_w1T + e * 64 + d);
            const float* xp = xs + e * 52 + t0;   // data at [1..12]
            float4 x0 = *(const float4*)(xp);
            float4 x1 = *(const float4*)(xp + 4);
            float4 x2 = *(const float4*)(xp + 8);
            float4 x3 = *(const float4*)(xp + 12);
            float xv[16] = {x0.x,x0.y,x0.z,x0.w, x1.x,x1.y,x1.z,x1.w,
                            x2.x,x2.y,x2.z,x2.w, x3.x,x3.y,x3.z,x3.w};
            #pragma unroll
            for (int j = 0; j < 12; j++) va[j] += w * xv[j + 1];
        }
        #pragma unroll
        for (int j = 0; j < 12; j++) vs[(t0 + j) * 68 + d] = va[j];
    }
    __syncthreads();   // qs, ks, vs ready

    // ---- attention: thread = (head-half, t); two sweeps of 4 heads
    const float scale = 0.35355339059327373f; // 1/sqrt(8)
    if (tid < 192) {
        const int t  = tid % 48;
        const int hh = tid / 48;       // 0..3
        #pragma unroll
        for (int sw = 0; sw < 2; sw++) {
            const int hd = (sw * 4 + hh) * 8;
            float q[8];
            #pragma unroll
            for (int dk = 0; dk < 8; dk++) q[dk] = qs[(hd + dk) * 52 + t];
            float s[48];
            #pragma unroll
            for (int u4 = 0; u4 < 12; u4++) {
                float4 a = make_float4(0.f, 0.f, 0.f, 0.f);
                #pragma unroll
                for (int dk = 0; dk < 8; dk++) {
                    float4 kv = *(const float4*)(ks + (hd + dk) * 52 + u4 * 4);
                    a.x += q[dk] * kv.x; a.y += q[dk] * kv.y;
                    a.z += q[dk] * kv.z; a.w += q[dk] * kv.w;
                }
                s[u4 * 4 + 0] = a.x * scale; s[u4 * 4 + 1] = a.y * scale;
                s[u4 * 4 + 2] = a.z * scale; s[u4 * 4 + 3] = a.w * scale;
            }
            float mx = s[0];
            #pragma unroll
            for (int u = 1; u < 48; u++) mx = fmaxf(mx, s[u]);
            float sum = 0.f;
            #pragma unroll
            for (int u = 0; u < 48; u++) { s[u] = __expf(s[u] - mx); sum += s[u]; }
            float inv = 1.f / sum;
            float4 a0 = make_float4(0.f, 0.f, 0.f, 0.f);
            float4 a1 = make_float4(0.f, 0.f, 0.f, 0.f);
            #pragma unroll
            for (int u = 0; u < 48; u++) {
                float p  = s[u];
                float4 v0 = *(const float4*)(vs + u * 68 + hd);
                float4 v1 = *(const float4*)(vs + u * 68 + hd + 4);
                a0.x += p * v0.x; a0.y += p * v0.y; a0.z += p * v0.z; a0.w += p * v0.w;
                a1.x += p * v1.x; a1.y += p * v1.y; a1.z += p * v1.z; a1.w += p * v1.w;
            }
            a0.x *= inv; a0.y *= inv; a0.z *= inv; a0.w *= inv;
            a1.x *= inv; a1.y *= inv; a1.z *= inv; a1.w *= inv;
            *(float4*)(aos + t * 68 + hd)     = a0;
            *(float4*)(aos + t * 68 + hd + 4) = a1;
        }
    }
    __syncthreads();

    // ---- y = ao @ W2^T + b2 (float4 over e, weights via LDG)
    {
        float ya[12];
        float b2v = __ldg(b2 + d);
        #pragma unroll
        for (int j = 0; j < 12; j++) ya[j] = b2v;
        #pragma unroll 2
        for (int e0 = 0; e0 < 64; e0 += 4) {
            const float* wp = g_w2T + e0 * 64 + d;
            float w0 = __ldg(wp);
            float w1 = __ldg(wp + 64);
            float w2 = __ldg(wp + 128);
            float w3 = __ldg(wp + 192);
            #pragma unroll
            for (int j = 0; j < 12; j++) {
                float4 a = *(const float4*)(aos + (t0 + j) * 68 + e0);
                ya[j] += a.x * w0 + a.y * w1 + a.z * w2 + a.w * w3;
            }
        }
        #pragma unroll
        for (int j = 0; j < 12; j++) ys[(t0 + j) * 68 + d] = ya[j];
    }
    __syncthreads();

    // ---- LayerNorm over d + residual x^T -> g_h
    float* hout = g_h + ((long)(b * 200 + n)) * 48 * 64;
    for (int t = warp; t < 48; t += 8) {
        float y1 = ys[t * 68 + lane];
        float y2 = ys[t * 68 + lane + 32];
        float s = y1 + y2;
        #pragma unroll
        for (int o = 16; o > 0; o >>= 1) s += __shfl_xor_sync(0xffffffffu, s, o);
        float mean = s * (1.f / 64.f);
        float d1 = y1 - mean, d2 = y2 - mean;
        float vv = d1 * d1 + d2 * d2;
        #pragma unroll
        for (int o = 16; o > 0; o >>= 1) vv += __shfl_xor_sync(0xffffffffu, vv, o);
        float rstd = rsqrtf(vv * (1.f / 64.f) + 1e-5f);
        float h1 = xs[lane * 52 + 1 + t]        + d1 * rstd * __ldg(g0 + lane)      + __ldg(beta0 + lane);
        float h2 = xs[(lane + 32) * 52 + 1 + t] + d2 * rstd * __ldg(g0 + lane + 32) + __ldg(beta0 + lane + 32);
        hout[t * 64 + lane]      = h1;
        hout[t * 64 + lane + 32] = h2;
    }
}

// ---------------------------------------------------------------------------
// Kernel 2: per (b, t, rowhalf). Spatial softmax-GCN, 100 rows/block.
// Softmax WITHOUT max-shift (scores bounded; softmax is shift-invariant):
// e = exp(s/8) directly, row-sum accumulated lane-locally, reduced once at
// the end. No rmax/fac/rescale, no shuffles inside the flash loop.
// smem floats: hs[200][68]@0 (13600), S[100][68]@13600 (6800; ThS[64][68]
// overlays) => 20400 floats = 81600 B  (2 blocks/SM)
// ---------------------------------------------------------------------------
__global__ void __launch_bounds__(256, 2) spatial_kernel(
    const float* __restrict__ adj, const float* __restrict__ Theta,
    const float* __restrict__ g1,  const float* __restrict__ beta1,
    float* __restrict__ out)
{
    extern __shared__ float sm[];
    float* hs = sm;            // [200][68]
    float* S  = sm + 13600;    // [100][68] P buffer; later ThS[64][68] dd-major

    const int t = blockIdx.x, b = blockIdx.y;
    const int r0 = blockIdx.z * 100;
    const int tid = threadIdx.x;
    const int tx = tid & 15, ty = tid >> 4;

    const float* hbase = g_h + (long)b * 200 * 48 * 64 + (long)t * 64;
    for (int i = tid; i < 3200; i += 256) {
        int nn = i >> 4, d4 = (i & 15) * 4;
        *(float4*)(hs + nn * 68 + d4) = *(const float4*)(hbase + (long)nn * 3072 + d4);
    }

    int  nl[7], slc[7];
    bool rv[7];
    #pragma unroll
    for (int r = 0; r < 7; r++) {
        int v = ty + 16 * r;
        rv[r]  = (v < 100);
        slc[r] = rv[r] ? v : 99;
        nl[r]  = slc[r];
    }

    float agg[7][4], rs[7];
    #pragma unroll
    for (int r = 0; r < 7; r++) {
        rs[r] = 0.f;
        #pragma unroll
        for (int c = 0; c < 4; c++) agg[r][c] = 0.f;
    }

    __syncthreads();   // hs ready

    for (int ci = 0; ci < 4; ci++) {
        const int m0 = ci * 64;
        const int MC = (ci == 3) ? 8 : 64;
        __syncwarp();  // P rows from previous chunk fully consumed

        // ---- scores: rows r0+nl[r], cols m = m0+tx+16c ----
        float sc[7][4];
        #pragma unroll
        for (int r = 0; r < 7; r++)
            #pragma unroll
            for (int c = 0; c < 4; c++) sc[r][c] = 0.f;
        int  mc[4]; bool mv[4];
        #pragma unroll
        for (int c = 0; c < 4; c++) {
            int m = m0 + tx + 16 * c;
            mv[c] = (m < 200);
            mc[c] = mv[c] ? m : 199;
        }
        for (int dd = 0; dd < 64; dd += 4) {
            float4 bb[4];
            #pragma unroll
            for (int c = 0; c < 4; c++)
                bb[c] = *(const float4*)(hs + mc[c] * 68 + dd);
            #pragma unroll
            for (int r = 0; r < 7; r++) {
                float4 av = *(const float4*)(hs + (r0 + slc[r]) * 68 + dd);
                #pragma unroll
                for (int c = 0; c < 4; c++)
                    sc[r][c] += av.x * bb[c].x + av.y * bb[c].y
                              + av.z * bb[c].z + av.w * bb[c].w;
            }
        }

        // ---- exp (no shift) + lane-local row-sum + P = e * adj ----
        #pragma unroll
        for (int r = 0; r < 7; r++) {
            float e[4];
            #pragma unroll
            for (int c = 0; c < 4; c++)
                e[c] = mv[c] ? __expf(sc[r][c] * 0.125f) : 0.f;
            rs[r] += (e[0] + e[1]) + (e[2] + e[3]);
            if (rv[r]) {
                const float* arow = adj + (long)(r0 + nl[r]) * 200 + m0;
                #pragma unroll
                for (int c = 0; c < 4; c++)
                    if (mv[c])
                        S[nl[r] * 68 + tx + 16 * c] = e[c] * __ldg(arow + tx + 16 * c);
            }
        }
        __syncwarp();   // P rows visible within owning half-warp

        // ---- agg += P_chunk @ h_chunk  (output cols dd = 4tx+c) ----
        for (int mb = 0; mb < MC; mb += 4) {
            float4 hb[4];
            #pragma unroll
            for (int j = 0; j < 4; j++)
                hb[j] = *(const float4*)(hs + (m0 + mb + j) * 68 + 4 * tx);
            #pragma unroll
            for (int r = 0; r < 7; r++) {
                float4 pw = *(const float4*)(S + slc[r] * 68 + mb);
                agg[r][0] += pw.x * hb[0].x + pw.y * hb[1].x + pw.z * hb[2].x + pw.w * hb[3].x;
                agg[r][1] += pw.x * hb[0].y + pw.y * hb[1].y + pw.z * hb[2].y + pw.w * hb[3].y;
                agg[r][2] += pw.x * hb[0].z + pw.y * hb[1].z + pw.z * hb[2].z + pw.w * hb[3].z;
                agg[r][3] += pw.x * hb[0].w + pw.y * hb[1].w + pw.z * hb[2].w + pw.w * hb[3].w;
            }
        }
    }

    __syncthreads();   // done reading hs / S everywhere

    // reduce row-sums across the 16 lanes, finalize agg /= (rsum * sqrt(D))
    #pragma unroll
    for (int r = 0; r < 7; r++) {
        float s = rs[r];
        #pragma unroll
        for (int o = 8; o > 0; o >>= 1)
            s += __shfl_xor_sync(0xffffffffu, s, o, 16);
        float inv = 1.f / (s * 8.f);
        if (rv[r]) {
            float4 v = make_float4(agg[r][0] * inv, agg[r][1] * inv,
                                   agg[r][2] * inv, agg[r][3] * inv);
            *(float4*)(hs + nl[r] * 68 + 4 * tx) = v;
        }
    }
    // stage Theta dd-major: ThS[dd*68 + j] = Theta[j][dd]
    for (int i = tid; i < 4096; i += 256)
        S[(i & 63) * 68 + (i >> 6)] = Theta[i];
    __syncthreads();

    // G = relu(agg @ Theta^T), thread cols j = 4tx+c
    float g[7][4];
    #pragma unroll
    for (int r = 0; r < 7; r++)
        #pragma unroll
        for (int c = 0; c < 4; c++) g[r][c] = 0.f;
    for (int dd = 0; dd < 64; dd += 4) {
        float4 tb[4];
        #pragma unroll
        for (int i = 0; i < 4; i++)
            tb[i] = *(const float4*)(S + (dd + i) * 68 + 4 * tx);
        #pragma unroll
        for (int r = 0; r < 7; r++) {
            float4 av = *(const float4*)(hs + slc[r] * 68 + dd);
            g[r][0] += av.x * tb[0].x + av.y * tb[1].x + av.z * tb[2].x + av.w * tb[3].x;
            g[r][1] += av.x * tb[0].y + av.y * tb[1].y + av.z * tb[2].y + av.w * tb[3].y;
            g[r][2] += av.x * tb[0].z + av.y * tb[1].z + av.z * tb[2].z + av.w * tb[3].z;
            g[r][3] += av.x * tb[0].w + av.y * tb[1].w + av.z * tb[2].w + av.w * tb[3].w;
        }
    }
    #pragma unroll
    for (int r = 0; r < 7; r++)
        #pragma unroll
        for (int c = 0; c < 4; c++) g[r][c] = fmaxf(g[r][c], 0.f);

    // LayerNorm over j + residual (float4 gmem) + store
    float* obase = out + (long)b * 200 * 3072 + (long)t * 64;
    float4 g1v = *(const float4*)(g1 + 4 * tx);
    float4 b1v = *(const float4*)(beta1 + 4 * tx);
    #pragma unroll
    for (int r = 0; r < 7; r++) {
        if (!rv[r]) continue;
        int ng = r0 + nl[r];
        float s = g[r][0] + g[r][1] + g[r][2] + g[r][3];
        #pragma unroll
        for (int o = 8; o > 0; o >>= 1) s += __shfl_xor_sync(0xffffffffu, s, o, 16);
        float mean = s * (1.f / 64.f);
        float vv = 0.f;
        #pragma unroll
        for (int c = 0; c < 4; c++) { float dg = g[r][c] - mean; vv += dg * dg; }
        #pragma unroll
        for (int o = 8; o > 0; o >>= 1) vv += __shfl_xor_sync(0xffffffffu, vv, o, 16);
        float rstd = rsqrtf(vv * (1.f / 64.f) + 1e-5f);
        float4 hv = *(const float4*)(hbase + (long)ng * 3072 + 4 * tx);
        float4 ov;
        ov.x = hv.x + (g[r][0] - mean) * rstd * g1v.x + b1v.x;
        ov.y = hv.y + (g[r][1] - mean) * rstd * g1v.y + b1v.y;
        ov.z = hv.z + (g[r][2] - mean) * rstd * g1v.z + b1v.z;
        ov.w = hv.w + (g[r][3] - mean) * rstd * g1v.w + b1v.w;
        *(float4*)(obase + (long)ng * 3072 + 4 * tx) = ov;
    }
}

// ---------------------------------------------------------------------------
extern "C" void kernel_launch(void* const* d_in, const int* in_sizes, int n_in,
                              void* d_out, int out_size)
{
    const float* x     = (const float*)d_in[0];
    const float* adj   = (const float*)d_in[1];
    const float* Wq    = (const float*)d_in[2];
    const float* bq    = (const float*)d_in[3];
    const float* Wk    = (const float*)d_in[4];
    const float* bk    = (const float*)d_in[5];
    const float* W1    = (const float*)d_in[6];
    const float* b1    = (const float*)d_in[7];
    const float* W2    = (const float*)d_in[8];
    const float* b2    = (const float*)d_in[9];
    const float* Theta = (const float*)d_in[10];
    const float* g0    = (const float*)d_in[11];
    const float* beta0 = (const float*)d_in[12];
    const float* g1    = (const float*)d_in[13];
    const float* beta1 = (const float*)d_in[14];
    float* out = (float*)d_out;

    const int SMEM_T = 19776 * 4;   // 79104 B
    const int SMEM_S = 20400 * 4;   // 81600 B
    cudaFuncSetAttribute(temporal_kernel,
                         cudaFuncAttributeMaxDynamicSharedMemorySize, SMEM_T);
    cudaFuncSetAttribute(spatial_kernel,
                         cudaFuncAttributeMaxDynamicSharedMemorySize, SMEM_S);

    prep_weights<<<48, 256>>>(Wq, Wk, W1, W2);
    temporal_kernel<<<dim3(NN, NB), 256, SMEM_T>>>(
        x, bq, bk, b1, b2, g0, beta0);
    spatial_kernel<<<dim3(NT, NB, 2), 256, SMEM_S>>>(
        adj, Theta, g1, beta1, out);
}

// round 13
// speedup vs baseline: 1.9000x; 1.2279x over previous
#include <cuda_runtime.h>

#define NB 16
#define ND 64
#define NN 200
#define NT 48
#define NH 8

// intermediate h = x^T + LN(temporal_out):  (B,N,T,D)
__device__ float g_h[NB * NN * NT * ND];

// pre-transposed weights (written by prep_weights each launch)
__device__ float2 g_wqkT[192 * 64];   // [(e*3+k)][d] -> (Wq, Wk)
__device__ float  g_w1T[64 * 64];     // [e][d] = W1[d][e]

__global__ void prep_weights(const float* __restrict__ Wq,
                             const float* __restrict__ Wk,
                             const float* __restrict__ W1)
{
    int i = blockIdx.x * 256 + threadIdx.x;
    if (i < 12288) {
        int r = i >> 6, d = i & 63;          // r = e*3+k
        float2 v;
        v.x = Wq[d * 192 + r];
        v.y = Wk[d * 192 + r];
        g_wqkT[i] = v;
    }
    if (i < 4096) {
        int e = i >> 6, d = i & 63;
        g_w1T[i] = W1[d * 64 + e];
    }
}

// ---- packed f32x2 helpers (Blackwell FFMA2 via PTX) ----
__device__ __forceinline__ float2 ffma2(float2 a, float2 b, float2 c) {
    float2 d;
    asm("fma.rn.f32x2 %0, %1, %2, %3;"
        : "=l"(*reinterpret_cast<unsigned long long*>(&d))
        : "l"(*reinterpret_cast<const unsigned long long*>(&a)),
          "l"(*reinterpret_cast<const unsigned long long*>(&b)),
          "l"(*reinterpret_cast<const unsigned long long*>(&c)));
    return d;
}
__device__ __forceinline__ float2 fdup(float s) { return make_float2(s, s); }
__device__ __forceinline__ float2 f2lo(float4 v) { return make_float2(v.x, v.y); }
__device__ __forceinline__ float2 f2hi(float4 v) { return make_float2(v.z, v.w); }

// ---------------------------------------------------------------------------
// Kernel 1: per (b, n). Fused conv1x3 q/k + v (single pass, packed f32x2),
// 8-head attention over T=48 (rows in registers, packed), W2 projection
// (packed dot over e), LayerNorm + residual -> g_h.
// smem floats: xs[64][52]@0, qs[64][52]@3328, ks[64][52]@6656, vs[48][68]@9984,
//              aos[48][68]@13248, ys[48][68]@16512, w2s[64][68]@19776
//              => 24128 floats = 96512 B  (2 blocks/SM)
// ---------------------------------------------------------------------------
__global__ void __launch_bounds__(256, 2) temporal_kernel(
    const float* __restrict__ x,  const float* __restrict__ W2,
    const float* __restrict__ bq, const float* __restrict__ bk,
    const float* __restrict__ b1, const float* __restrict__ b2,
    const float* __restrict__ g0, const float* __restrict__ beta0)
{
    extern __shared__ float sm[];
    float* xs   = sm;            // [64][52], col0/col49 zero pad
    float* qs   = sm + 3328;     // [64][52]
    float* ks   = sm + 6656;     // [64][52]
    float* vs   = sm + 9984;     // [48][68]
    float* aos  = sm + 13248;    // [48][68]
    float* ys   = sm + 16512;    // [48][68]
    float* w2s  = sm + 19776;    // [64][68]  W2 rows (row-major)

    const int n   = blockIdx.x;
    const int b   = blockIdx.y;
    const int tid = threadIdx.x;
    const int d   = tid & 63;
    const int t0  = (tid >> 6) * 12;
    const int lane = tid & 31;
    const int warp = tid >> 5;

    // load x tile: x[b][e][n][t] -> xs[e][1+t]
    const float* xbase = x + ((long)(b * 64) * 200 + n) * 48;
    for (int i = tid; i < 64 * 48; i += 256) {
        int e = i / 48, t = i % 48;
        xs[e * 52 + 1 + t] = xbase[(long)e * 9600 + t];
    }
    if (tid < 128) {
        int e = tid & 63;
        xs[e * 52 + ((tid < 64) ? 0 : 49)] = 0.f;
    }
    // stage W2 rows into smem (row-major, stride 68)
    for (int i = tid; i < 1024; i += 256) {
        int dd = i >> 4, e0 = (i & 15) * 4;
        *(float4*)(w2s + dd * 68 + e0) = *(const float4*)(W2 + dd * 64 + e0);
    }
    __syncthreads();   // xs, w2s ready

    // ---- fused conv1x3 q/k (packed over (q,k)) + v (scalar), single pass
    float2 qk[12];
    float  va[12];
    #pragma unroll
    for (int j = 0; j < 12; j++) { qk[j] = make_float2(0.f, 0.f); va[j] = 0.f; }

    #pragma unroll 2
    for (int el = 0; el < 64; el++) {
        const float2* wr = g_wqkT + el * 192 + d;
        float2 w0 = __ldg(wr);
        float2 w1 = __ldg(wr + 64);
        float2 w2 = __ldg(wr + 128);
        float  wv = __ldg(g_w1T + el * 64 + d);
        const float* xp = xs + el * 52 + t0;   // aligned; taps at [0..13]
        float4 x0 = *(const float4*)(xp);
        float4 x1 = *(const float4*)(xp + 4);
        float4 x2 = *(const float4*)(xp + 8);
        float4 x3 = *(const float4*)(xp + 12);
        float xv[16] = {x0.x,x0.y,x0.z,x0.w, x1.x,x1.y,x1.z,x1.w,
                        x2.x,x2.y,x2.z,x2.w, x3.x,x3.y,x3.z,x3.w};
        float2 xd[14];
        #pragma unroll
        for (int j = 0; j < 14; j++) xd[j] = fdup(xv[j]);
        #pragma unroll
        for (int j = 0; j < 12; j++) {
            qk[j] = ffma2(xd[j],     w0, qk[j]);
            qk[j] = ffma2(xd[j + 1], w1, qk[j]);
            qk[j] = ffma2(xd[j + 2], w2, qk[j]);
            va[j] += wv * xv[j + 1];
        }
    }
    {
        float bqv = __ldg(bq + d), bkv = __ldg(bk + d), b1v = __ldg(b1 + d);
        #pragma unroll
        for (int j = 0; j < 12; j++) {
            qs[d * 52 + t0 + j] = qk[j].x + bqv;
            ks[d * 52 + t0 + j] = qk[j].y + bkv;
            vs[(t0 + j) * 68 + d] = va[j] + b1v;
        }
    }
    __syncthreads();   // qs, ks, vs ready

    // ---- attention: thread = (head-half, t); two sweeps of 4 heads
    const float scale = 0.35355339059327373f; // 1/sqrt(8)
    if (tid < 192) {
        const int t  = tid % 48;
        const int hh = tid / 48;       // 0..3
        #pragma unroll
        for (int sw = 0; sw < 2; sw++) {
            const int hd = (sw * 4 + hh) * 8;
            float2 qd[8];
            #pragma unroll
            for (int dk = 0; dk < 8; dk++)
                qd[dk] = fdup(qs[(hd + dk) * 52 + t] * scale);
            float2 s2[24];
            #pragma unroll
            for (int i = 0; i < 24; i++) s2[i] = make_float2(0.f, 0.f);
            #pragma unroll
            for (int u4 = 0; u4 < 12; u4++) {
                #pragma unroll
                for (int dk = 0; dk < 8; dk++) {
                    float4 kv = *(const float4*)(ks + (hd + dk) * 52 + u4 * 4);
                    s2[2 * u4]     = ffma2(qd[dk], f2lo(kv), s2[2 * u4]);
                    s2[2 * u4 + 1] = ffma2(qd[dk], f2hi(kv), s2[2 * u4 + 1]);
                }
            }
            // softmax in registers
            float mx = -1e30f;
            #pragma unroll
            for (int i = 0; i < 24; i++)
                mx = fmaxf(mx, fmaxf(s2[i].x, s2[i].y));
            float sum = 0.f;
            #pragma unroll
            for (int i = 0; i < 24; i++) {
                s2[i].x = __expf(s2[i].x - mx);
                s2[i].y = __expf(s2[i].y - mx);
                sum += s2[i].x + s2[i].y;
            }
            float inv = 1.f / sum;
            // PV (packed over d)
            float2 a0l = make_float2(0.f, 0.f), a0h = a0l, a1l = a0l, a1h = a0l;
            #pragma unroll
            for (int i = 0; i < 24; i++) {
                int u = 2 * i;
                float2 p0 = fdup(s2[i].x), p1 = fdup(s2[i].y);
                float4 v00 = *(const float4*)(vs + u * 68 + hd);
                float4 v01 = *(const float4*)(vs + u * 68 + hd + 4);
                float4 v10 = *(const float4*)(vs + (u + 1) * 68 + hd);
                float4 v11 = *(const float4*)(vs + (u + 1) * 68 + hd + 4);
                a0l = ffma2(p0, f2lo(v00), a0l); a0h = ffma2(p0, f2hi(v00), a0h);
                a1l = ffma2(p0, f2lo(v01), a1l); a1h = ffma2(p0, f2hi(v01), a1h);
                a0l = ffma2(p1, f2lo(v10), a0l); a0h = ffma2(p1, f2hi(v10), a0h);
                a1l = ffma2(p1, f2lo(v11), a1l); a1h = ffma2(p1, f2hi(v11), a1h);
            }
            float4 o0 = make_float4(a0l.x * inv, a0l.y * inv, a0h.x * inv, a0h.y * inv);
            float4 o1 = make_float4(a1l.x * inv, a1l.y * inv, a1h.x * inv, a1h.y * inv);
            *(float4*)(aos + t * 68 + hd)     = o0;
            *(float4*)(aos + t * 68 + hd + 4) = o1;
        }
    }
    __syncthreads();

    // ---- y = ao @ W2^T + b2 (packed dot over e)
    {
        float2 ya2[12];
        #pragma unroll
        for (int j = 0; j < 12; j++) ya2[j] = make_float2(0.f, 0.f);
        #pragma unroll 4
        for (int e0 = 0; e0 < 64; e0 += 4) {
            float4 w = *(const float4*)(w2s + d * 68 + e0);
            float2 wl = f2lo(w), wh = f2hi(w);
            #pragma unroll
            for (int j = 0; j < 12; j++) {
                float4 a = *(const float4*)(aos + (t0 + j) * 68 + e0);
                ya2[j] = ffma2(wl, f2lo(a), ya2[j]);
                ya2[j] = ffma2(wh, f2hi(a), ya2[j]);
            }
        }
        float b2v = __ldg(b2 + d);
        #pragma unroll
        for (int j = 0; j < 12; j++)
            ys[(t0 + j) * 68 + d] = ya2[j].x + ya2[j].y + b2v;
    }
    __syncthreads();

    // ---- LayerNorm over d + residual x^T -> g_h
    float* hout = g_h + ((long)(b * 200 + n)) * 48 * 64;
    for (int t = warp; t < 48; t += 8) {
        float y1 = ys[t * 68 + lane];
        float y2 = ys[t * 68 + lane + 32];
        float s = y1 + y2;
        #pragma unroll
        for (int o = 16; o > 0; o >>= 1) s += __shfl_xor_sync(0xffffffffu, s, o);
        float mean = s * (1.f / 64.f);
        float d1 = y1 - mean, d2 = y2 - mean;
        float vv = d1 * d1 + d2 * d2;
        #pragma unroll
        for (int o = 16; o > 0; o >>= 1) vv += __shfl_xor_sync(0xffffffffu, vv, o);
        float rstd = rsqrtf(vv * (1.f / 64.f) + 1e-5f);
        float h1 = xs[lane * 52 + 1 + t]        + d1 * rstd * __ldg(g0 + lane)      + __ldg(beta0 + lane);
        float h2 = xs[(lane + 32) * 52 + 1 + t] + d2 * rstd * __ldg(g0 + lane + 32) + __ldg(beta0 + lane + 32);
        hout[t * 64 + lane]      = h1;
        hout[t * 64 + lane + 32] = h2;
    }
}

// ---------------------------------------------------------------------------
// Kernel 2: per (b, t, rowhalf). Spatial softmax-GCN, 100 rows/block.
// Packed f32x2 everywhere: scores/Theta = dot-over-dd pairs, agg = dup(P)*h.
// Softmax without max-shift; lane-local row-sums reduced once at the end.
// smem floats: hs[200][68]@0 (13600), S[100][68]@13600 (6800; ThS[64][68]
// overlays) => 20400 floats = 81600 B  (2 blocks/SM)
// ---------------------------------------------------------------------------
__global__ void __launch_bounds__(256, 2) spatial_kernel(
    const float* __restrict__ adj, const float* __restrict__ Theta,
    const float* __restrict__ g1,  const float* __restrict__ beta1,
    float* __restrict__ out)
{
    extern __shared__ float sm[];
    float* hs = sm;            // [200][68]
    float* S  = sm + 13600;    // [100][68] P buffer; later ThS[64][68] dd-major

    const int t = blockIdx.x, b = blockIdx.y;
    const int r0 = blockIdx.z * 100;
    const int tid = threadIdx.x;
    const int tx = tid & 15, ty = tid >> 4;

    const float* hbase = g_h + (long)b * 200 * 48 * 64 + (long)t * 64;
    for (int i = tid; i < 3200; i += 256) {
        int nn = i >> 4, d4 = (i & 15) * 4;
        *(float4*)(hs + nn * 68 + d4) = *(const float4*)(hbase + (long)nn * 3072 + d4);
    }

    int  nl[7], slc[7];
    bool rv[7];
    #pragma unroll
    for (int r = 0; r < 7; r++) {
        int v = ty + 16 * r;
        rv[r]  = (v < 100);
        slc[r] = rv[r] ? v : 99;
        nl[r]  = slc[r];
    }

    float2 agg2[7][2];
    float  rs[7];
    #pragma unroll
    for (int r = 0; r < 7; r++) {
        rs[r] = 0.f;
        agg2[r][0] = make_float2(0.f, 0.f);
        agg2[r][1] = make_float2(0.f, 0.f);
    }

    __syncthreads();   // hs ready

    for (int ci = 0; ci < 4; ci++) {
        const int m0 = ci * 64;
        const int MC = (ci == 3) ? 8 : 64;
        __syncwarp();  // P rows from previous chunk fully consumed

        // ---- scores (packed dot over dd): rows r0+nl[r], cols m0+tx+16c ----
        float2 sc2[7][4];
        #pragma unroll
        for (int r = 0; r < 7; r++)
            #pragma unroll
            for (int c = 0; c < 4; c++) sc2[r][c] = make_float2(0.f, 0.f);
        int  mc[4]; bool mv[4];
        #pragma unroll
        for (int c = 0; c < 4; c++) {
            int m = m0 + tx + 16 * c;
            mv[c] = (m < 200);
            mc[c] = mv[c] ? m : 199;
        }
        for (int dd = 0; dd < 64; dd += 4) {
            float4 bb[4];
            #pragma unroll
            for (int c = 0; c < 4; c++)
                bb[c] = *(const float4*)(hs + mc[c] * 68 + dd);
            #pragma unroll
            for (int r = 0; r < 7; r++) {
                float4 av = *(const float4*)(hs + (r0 + slc[r]) * 68 + dd);
                float2 al = f2lo(av), ah = f2hi(av);
                #pragma unroll
                for (int c = 0; c < 4; c++) {
                    sc2[r][c] = ffma2(al, f2lo(bb[c]), sc2[r][c]);
                    sc2[r][c] = ffma2(ah, f2hi(bb[c]), sc2[r][c]);
                }
            }
        }

        // ---- exp (no shift) + lane-local row-sum + P = e * adj ----
        #pragma unroll
        for (int r = 0; r < 7; r++) {
            float e[4];
            #pragma unroll
            for (int c = 0; c < 4; c++) {
                float sv = (sc2[r][c].x + sc2[r][c].y) * 0.125f;
                e[c] = mv[c] ? __expf(sv) : 0.f;
            }
            rs[r] += (e[0] + e[1]) + (e[2] + e[3]);
            if (rv[r]) {
                const float* arow = adj + (long)(r0 + nl[r]) * 200 + m0;
                #pragma unroll
                for (int c = 0; c < 4; c++)
                    if (mv[c])
                        S[nl[r] * 68 + tx + 16 * c] = e[c] * __ldg(arow + tx + 16 * c);
            }
        }
        __syncwarp();   // P rows visible within owning half-warp

        // ---- agg += P_chunk @ h_chunk (dup(P) * packed h, cols dd=4tx+c) ----
        for (int mb = 0; mb < MC; mb += 4) {
            float4 hb[4];
            #pragma unroll
            for (int j = 0; j < 4; j++)
                hb[j] = *(const float4*)(hs + (m0 + mb + j) * 68 + 4 * tx);
            #pragma unroll
            for (int r = 0; r < 7; r++) {
                float4 pw = *(const float4*)(S + slc[r] * 68 + mb);
                float2 p0 = fdup(pw.x), p1 = fdup(pw.y), p2 = fdup(pw.z), p3 = fdup(pw.w);
                agg2[r][0] = ffma2(p0, f2lo(hb[0]), agg2[r][0]);
                agg2[r][1] = ffma2(p0, f2hi(hb[0]), agg2[r][1]);
                agg2[r][0] = ffma2(p1, f2lo(hb[1]), agg2[r][0]);
                agg2[r][1] = ffma2(p1, f2hi(hb[1]), agg2[r][1]);
                agg2[r][0] = ffma2(p2, f2lo(hb[2]), agg2[r][0]);
                agg2[r][1] = ffma2(p2, f2hi(hb[2]), agg2[r][1]);
                agg2[r][0] = ffma2(p3, f2lo(hb[3]), agg2[r][0]);
                agg2[r][1] = ffma2(p3, f2hi(hb[3]), agg2[r][1]);
            }
        }
    }

    __syncthreads();   // done reading hs / S everywhere

    // reduce row-sums across the 16 lanes, finalize agg /= (rsum * sqrt(D))
    #pragma unroll
    for (int r = 0; r < 7; r++) {
        float s = rs[r];
        #pragma unroll
        for (int o = 8; o > 0; o >>= 1)
            s += __shfl_xor_sync(0xffffffffu, s, o, 16);
        float inv = 1.f / (s * 8.f);
        if (rv[r]) {
            float4 v = make_float4(agg2[r][0].x * inv, agg2[r][0].y * inv,
                                   agg2[r][1].x * inv, agg2[r][1].y * inv);
            *(float4*)(hs + nl[r] * 68 + 4 * tx) = v;
        }
    }
    // stage Theta dd-major: ThS[dd*68 + j] = Theta[j][dd]
    for (int i = tid; i < 4096; i += 256)
        S[(i & 63) * 68 + (i >> 6)] = Theta[i];
    __syncthreads();

    // G = relu(agg @ Theta^T): dup(agg) * packed Theta (lanes = j-pairs)
    float2 g2[7][2];
    #pragma unroll
    for (int r = 0; r < 7; r++) {
        g2[r][0] = make_float2(0.f, 0.f);
        g2[r][1] = make_float2(0.f, 0.f);
    }
    for (int dd = 0; dd < 64; dd += 4) {
        float4 tb[4];
        #pragma unroll
        for (int i = 0; i < 4; i++)
            tb[i] = *(const float4*)(S + (dd + i) * 68 + 4 * tx);
        #pragma unroll
        for (int r = 0; r < 7; r++) {
            float4 av = *(const float4*)(hs + slc[r] * 68 + dd);
            float2 a0 = fdup(av.x), a1 = fdup(av.y), a2 = fdup(av.z), a3 = fdup(av.w);
            g2[r][0] = ffma2(a0, f2lo(tb[0]), g2[r][0]);
            g2[r][1] = ffma2(a0, f2hi(tb[0]), g2[r][1]);
            g2[r][0] = ffma2(a1, f2lo(tb[1]), g2[r][0]);
            g2[r][1] = ffma2(a1, f2hi(tb[1]), g2[r][1]);
            g2[r][0] = ffma2(a2, f2lo(tb[2]), g2[r][0]);
            g2[r][1] = ffma2(a2, f2hi(tb[2]), g2[r][1]);
            g2[r][0] = ffma2(a3, f2lo(tb[3]), g2[r][0]);
            g2[r][1] = ffma2(a3, f2hi(tb[3]), g2[r][1]);
        }
    }
    float g[7][4];
    #pragma unroll
    for (int r = 0; r < 7; r++) {
        g[r][0] = fmaxf(g2[r][0].x, 0.f);
        g[r][1] = fmaxf(g2[r][0].y, 0.f);
        g[r][2] = fmaxf(g2[r][1].x, 0.f);
        g[r][3] = fmaxf(g2[r][1].y, 0.f);
    }

    // LayerNorm over j + residual (float4 gmem) + store
    float* obase = out + (long)b * 200 * 3072 + (long)t * 64;
    float4 g1v = *(const float4*)(g1 + 4 * tx);
    float4 b1v = *(const float4*)(beta1 + 4 * tx);
    #pragma unroll
    for (int r = 0; r < 7; r++) {
        if (!rv[r]) continue;
        int ng = r0 + nl[r];
        float s = g[r][0] + g[r][1] + g[r][2] + g[r][3];
        #pragma unroll
        for (int o = 8; o > 0; o >>= 1) s += __shfl_xor_sync(0xffffffffu, s, o, 16);
        float mean = s * (1.f / 64.f);
        float vv = 0.f;
        #pragma unroll
        for (int c = 0; c < 4; c++) { float dg = g[r][c] - mean; vv += dg * dg; }
        #pragma unroll
        for (int o = 8; o > 0; o >>= 1) vv += __shfl_xor_sync(0xffffffffu, vv, o, 16);
        float rstd = rsqrtf(vv * (1.f / 64.f) + 1e-5f);
        float4 hv = *(const float4*)(hbase + (long)ng * 3072 + 4 * tx);
        float4 ov;
        ov.x = hv.x + (g[r][0] - mean) * rstd * g1v.x + b1v.x;
        ov.y = hv.y + (g[r][1] - mean) * rstd * g1v.y + b1v.y;
        ov.z = hv.z + (g[r][2] - mean) * rstd * g1v.z + b1v.z;
        ov.w = hv.w + (g[r][3] - mean) * rstd * g1v.w + b1v.w;
        *(float4*)(obase + (long)ng * 3072 + 4 * tx) = ov;
    }
}

// ---------------------------------------------------------------------------
extern "C" void kernel_launch(void* const* d_in, const int* in_sizes, int n_in,
                              void* d_out, int out_size)
{
    const float* x     = (const float*)d_in[0];
    const float* adj   = (const float*)d_in[1];
    const float* Wq    = (const float*)d_in[2];
    const float* bq    = (const float*)d_in[3];
    const float* Wk    = (const float*)d_in[4];
    const float* bk    = (const float*)d_in[5];
    const float* W1    = (const float*)d_in[6];
    const float* b1    = (const float*)d_in[7];
    const float* W2    = (const float*)d_in[8];
    const float* b2    = (const float*)d_in[9];
    const float* Theta = (const float*)d_in[10];
    const float* g0    = (const float*)d_in[11];
    const float* beta0 = (const float*)d_in[12];
    const float* g1    = (const float*)d_in[13];
    const float* beta1 = (const float*)d_in[14];
    float* out = (float*)d_out;

    const int SMEM_T = 24128 * 4;   // 96512 B
    const int SMEM_S = 20400 * 4;   // 81600 B
    cudaFuncSetAttribute(temporal_kernel,
                         cudaFuncAttributeMaxDynamicSharedMemorySize, SMEM_T);
    cudaFuncSetAttribute(spatial_kernel,
                         cudaFuncAttributeMaxDynamicSharedMemorySize, SMEM_S);

    prep_weights<<<48, 256>>>(Wq, Wk, W1);
    temporal_kernel<<<dim3(NN, NB), 256, SMEM_T>>>(
        x, W2, bq, bk, b1, b2, g0, beta0);
    spatial_kernel<<<dim3(NT, NB, 2), 256, SMEM_S>>>(
        adj, Theta, g1, beta1, out);
}